// round 1
// baseline (speedup 1.0000x reference)
#include <cuda_runtime.h>
#include <math.h>

// Problem constants: B=4, L=1024, DM=768, DC=256, N=16, R=48, K=4, H=8, HD=32
#define MTOT 4096            // B*L

// ---------------- scratch (static device arrays; no allocation) ----------------
__device__ float g_xzy[MTOT * 768];
__device__ float g_xc[MTOT * 256];
__device__ float g_yc[MTOT * 256];
__device__ float g_cat[MTOT * 768];
__device__ float g_xdbl[MTOT * 80];
__device__ float g_delta[MTOT * 256];
__device__ float g_qkv[MTOT * 768];
__device__ float g_S[32ll * 1024 * 1024];   // (B*H, L, L) attention scores
__device__ float g_o[MTOT * 256];

// ---------------- generic NT GEMM: C = alpha * A(MxK) @ B(NxK)^T [+ epi] ----------------
// epi: 0 = none, 1 = +bias*bscale, 2 = softplus(v + bias*bscale)
// batching: per blockIdx.z, ptr += (z/zdiv)*s?0 + (z%zdiv)*s?1
__global__ void __launch_bounds__(256) gemm_nt(
    const float* __restrict__ A, const float* __restrict__ B, float* __restrict__ C,
    int M, int N, int K, int lda, int ldb, int ldc, int coff,
    const float* __restrict__ bias, float bscale, float alpha, int epi,
    int zdiv, long long sA0, long long sA1, long long sB0, long long sB1,
    long long sC0, long long sC1)
{
    __shared__ float As[16][68];
    __shared__ float Bs[16][68];
    int z = blockIdx.z;
    A += (long long)(z / zdiv) * sA0 + (long long)(z % zdiv) * sA1;
    B += (long long)(z / zdiv) * sB0 + (long long)(z % zdiv) * sB1;
    C += (long long)(z / zdiv) * sC0 + (long long)(z % zdiv) * sC1;

    int tid = threadIdx.x;
    int tx = tid & 15, ty = tid >> 4;
    int row0 = blockIdx.y * 64;
    int col0 = blockIdx.x * 64;
    float acc[4][4] = {};

    for (int k0 = 0; k0 < K; k0 += 16) {
        #pragma unroll
        for (int i = 0; i < 4; i++) {
            int idx = tid * 4 + i;          // 0..1023 over the 64x16 tile
            int r = idx >> 4, kk = idx & 15;
            int gk = k0 + kk;
            int gr = row0 + r;
            float va = 0.f;
            if (gr < M && gk < K) va = A[(long long)gr * lda + gk];
            As[kk][r] = va;
            int gc = col0 + r;
            float vb = 0.f;
            if (gc < N && gk < K) vb = B[(long long)gc * ldb + gk];
            Bs[kk][r] = vb;
        }
        __syncthreads();
        #pragma unroll
        for (int kk = 0; kk < 16; kk++) {
            float4 a4 = *(const float4*)&As[kk][ty * 4];
            float4 b4 = *(const float4*)&Bs[kk][tx * 4];
            float av[4] = {a4.x, a4.y, a4.z, a4.w};
            float bv[4] = {b4.x, b4.y, b4.z, b4.w};
            #pragma unroll
            for (int i = 0; i < 4; i++)
                #pragma unroll
                for (int j = 0; j < 4; j++)
                    acc[i][j] = fmaf(av[i], bv[j], acc[i][j]);
        }
        __syncthreads();
    }

    #pragma unroll
    for (int i = 0; i < 4; i++) {
        int r = row0 + ty * 4 + i;
        if (r >= M) continue;
        #pragma unroll
        for (int j = 0; j < 4; j++) {
            int c = col0 + tx * 4 + j;
            if (c >= N) continue;
            float v = acc[i][j] * alpha;
            if (epi >= 1) v += bias[c] * bscale;
            if (epi == 2) v = (v > 15.f) ? v : log1pf(__expf(v));
            C[(long long)r * ldc + coff + c] = v;
        }
    }
}

// ------------- depthwise conv (K=4, pad left 1 / right 2) + SiLU, all 3 branches -------------
__global__ void __launch_bounds__(256) conv_silu_kernel(
    const float* __restrict__ xzy,
    const float* __restrict__ wx, const float* __restrict__ wz, const float* __restrict__ wy,
    float* __restrict__ xc, float* __restrict__ cat, float* __restrict__ yc)
{
    int idx = blockIdx.x * 256 + threadIdx.x;   // m*256 + d
    int d = idx & 255;
    int m = idx >> 8;
    int l = m & 1023;
    const float* base = xzy + (long long)m * 768;
    float a0 = 0.f, a1 = 0.f, a2 = 0.f;
    #pragma unroll
    for (int k = 0; k < 4; k++) {
        int li = l + k - 1;
        if (li < 0 || li >= 1024) continue;
        const float* row = base + (long long)(k - 1) * 768;
        a0 = fmaf(row[d],       wx[d * 4 + k], a0);
        a1 = fmaf(row[256 + d], wz[d * 4 + k], a1);
        a2 = fmaf(row[512 + d], wy[d * 4 + k], a2);
    }
    a0 = a0 / (1.f + __expf(-a0));
    a1 = a1 / (1.f + __expf(-a1));
    a2 = a2 / (1.f + __expf(-a2));
    xc[idx] = a0;
    cat[(long long)m * 768 + 256 + d] = a1;   // gating branch -> concat cols [256,512)
    yc[idx] = a2;
}

// ------------- selective scan: 16 lanes = 16 states per (b,d) pair -------------
__global__ void __launch_bounds__(256) scan_kernel(
    const float* __restrict__ delta, const float* __restrict__ xc,
    const float* __restrict__ xdbl, const float* __restrict__ A_log,
    const float* __restrict__ D_param, float* __restrict__ cat)
{
    int t = blockIdx.x * 256 + threadIdx.x;
    int lane = t & 15;
    int p = t >> 4;              // 0..1023 = b*256 + d
    int b = p >> 8;
    int d = p & 255;
    float Acoef = -__expf(A_log[d * 16 + lane]);   // A[d,n]
    float Dd = D_param[d];
    float h = 0.f;
    const float* dptr = delta + (long long)b * 1024 * 256 + d;
    const float* xptr = xc    + (long long)b * 1024 * 256 + d;
    const float* bptr = xdbl  + (long long)b * 1024 * 80 + 48 + lane;   // B_l[n]
    const float* cptr = bptr + 16;                                      // C_l[n]
    float* optr = cat + (long long)b * 1024 * 768 + d;                  // concat cols [0,256)
    #pragma unroll 4
    for (int l = 0; l < 1024; l++) {
        float dl = dptr[(long long)l * 256];
        float xv = xptr[(long long)l * 256];
        float Bv = bptr[(long long)l * 80];
        float Cv = cptr[(long long)l * 80];
        float dA = __expf(dl * Acoef);
        h = fmaf(dA, h, dl * xv * Bv);
        float yv = h * Cv;
        yv += __shfl_xor_sync(0xffffffffu, yv, 1);
        yv += __shfl_xor_sync(0xffffffffu, yv, 2);
        yv += __shfl_xor_sync(0xffffffffu, yv, 4);
        yv += __shfl_xor_sync(0xffffffffu, yv, 8);
        if (lane == 0) optr[(long long)l * 768] = fmaf(xv, Dd, yv);
    }
}

// ------------- row softmax over 1024 columns (one block per row) -------------
__global__ void __launch_bounds__(128) softmax_kernel(float* __restrict__ S)
{
    long long row = blockIdx.x;
    float* p = S + row * 1024;
    int t = threadIdx.x;
    float v[8];
    float m = -1e30f;
    #pragma unroll
    for (int i = 0; i < 8; i++) { v[i] = p[t + i * 128]; m = fmaxf(m, v[i]); }
    #pragma unroll
    for (int o = 16; o; o >>= 1) m = fmaxf(m, __shfl_xor_sync(0xffffffffu, m, o));
    __shared__ float red[4], red2[4];
    if ((t & 31) == 0) red[t >> 5] = m;
    __syncthreads();
    m = fmaxf(fmaxf(red[0], red[1]), fmaxf(red[2], red[3]));
    float s = 0.f;
    #pragma unroll
    for (int i = 0; i < 8; i++) { v[i] = __expf(v[i] - m); s += v[i]; }
    #pragma unroll
    for (int o = 16; o; o >>= 1) s += __shfl_xor_sync(0xffffffffu, s, o);
    if ((t & 31) == 0) red2[t >> 5] = s;
    __syncthreads();
    s = red2[0] + red2[1] + red2[2] + red2[3];
    float inv = 1.f / s;
    #pragma unroll
    for (int i = 0; i < 8; i++) p[t + i * 128] = v[i] * inv;
}

// ------------- O = P @ V per head (M=1024, N=32, K=1024) -------------
__global__ void __launch_bounds__(256) attn_out_kernel(
    const float* __restrict__ S, const float* __restrict__ qkv, float* __restrict__ obuf)
{
    int z = blockIdx.y;          // b*8 + h
    int b = z >> 3, hh = z & 7;
    int q0 = blockIdx.x * 64;
    const float* Sp = S + (long long)z * 1024 * 1024 + (long long)q0 * 1024;
    const float* Vp = qkv + (long long)b * 1024 * 768 + 512 + hh * 32;
    __shared__ float Ps[64][65];
    __shared__ float Vs[64][33];
    int t = threadIdx.x;
    int c2 = (t & 15) * 2;       // 2 head-dim cols per thread
    int rg = t >> 4;             // 16 row groups of 4
    float acc[4][2] = {};
    for (int k0 = 0; k0 < 1024; k0 += 64) {
        #pragma unroll
        for (int i = 0; i < 16; i++) {
            int idx = t + i * 256;
            int r = idx >> 6, kk = idx & 63;
            Ps[r][kk] = Sp[(long long)r * 1024 + k0 + kk];
        }
        #pragma unroll
        for (int i = 0; i < 8; i++) {
            int idx = t + i * 256;
            int r = idx >> 5, hd = idx & 31;
            Vs[r][hd] = Vp[(long long)(k0 + r) * 768 + hd];
        }
        __syncthreads();
        #pragma unroll 2
        for (int kk = 0; kk < 64; kk++) {
            float v0 = Vs[kk][c2];
            float v1 = Vs[kk][c2 + 1];
            #pragma unroll
            for (int i = 0; i < 4; i++) {
                float pv = Ps[rg * 4 + i][kk];
                acc[i][0] = fmaf(pv, v0, acc[i][0]);
                acc[i][1] = fmaf(pv, v1, acc[i][1]);
            }
        }
        __syncthreads();
    }
    float* op = obuf + (long long)(b * 1024 + q0) * 256 + hh * 32;
    #pragma unroll
    for (int i = 0; i < 4; i++) {
        op[(long long)(rg * 4 + i) * 256 + c2]     = acc[i][0];
        op[(long long)(rg * 4 + i) * 256 + c2 + 1] = acc[i][1];
    }
}

// ---------------- host launcher ----------------
extern "C" void kernel_launch(void* const* d_in, const int* in_sizes, int n_in,
                              void* d_out, int out_size)
{
    const float* hs          = (const float*)d_in[0];
    const float* in_proj_w   = (const float*)d_in[1];
    const float* conv_wx     = (const float*)d_in[2];
    const float* conv_wz     = (const float*)d_in[3];
    const float* conv_wy     = (const float*)d_in[4];
    const float* x_proj_w    = (const float*)d_in[5];
    const float* dt_proj_w   = (const float*)d_in[6];
    const float* dt_proj_b   = (const float*)d_in[7];
    const float* A_log       = (const float*)d_in[8];
    const float* D_param     = (const float*)d_in[9];
    const float* out_proj_w  = (const float*)d_in[10];
    const float* qkv_w       = (const float*)d_in[11];
    const float* attn_proj_w = (const float*)d_in[12];
    const float* attn_proj_b = (const float*)d_in[13];
    float* out = (float*)d_out;

    float *xzy, *xc, *yc, *cat, *xdbl, *delta, *qkv, *S, *o;
    cudaGetSymbolAddress((void**)&xzy,   g_xzy);
    cudaGetSymbolAddress((void**)&xc,    g_xc);
    cudaGetSymbolAddress((void**)&yc,    g_yc);
    cudaGetSymbolAddress((void**)&cat,   g_cat);
    cudaGetSymbolAddress((void**)&xdbl,  g_xdbl);
    cudaGetSymbolAddress((void**)&delta, g_delta);
    cudaGetSymbolAddress((void**)&qkv,   g_qkv);
    cudaGetSymbolAddress((void**)&S,     g_S);
    cudaGetSymbolAddress((void**)&o,     g_o);

    dim3 blk(256);

    // 1) xzy = hs @ in_proj_w^T          (4096,768) x (768,768)
    gemm_nt<<<dim3(12, 64, 1), blk>>>(hs, in_proj_w, xzy, 4096, 768, 768,
        768, 768, 768, 0, nullptr, 0.f, 1.f, 0, 1, 0, 0, 0, 0, 0, 0);

    // 2) depthwise conv + SiLU for x/z/y (z -> cat cols [256,512))
    conv_silu_kernel<<<4096, 256>>>(xzy, conv_wx, conv_wz, conv_wy, xc, cat, yc);

    // 3) x_dbl = xc @ x_proj_w^T         (4096,80)
    gemm_nt<<<dim3(2, 64, 1), blk>>>(xc, x_proj_w, xdbl, 4096, 80, 256,
        256, 256, 80, 0, nullptr, 0.f, 1.f, 0, 1, 0, 0, 0, 0, 0, 0);

    // 4) delta = softplus(dt @ dt_proj_w^T + 2*dt_proj_b)   (4096,256), K=48 (lda=80)
    gemm_nt<<<dim3(4, 64, 1), blk>>>(xdbl, dt_proj_w, delta, 4096, 256, 48,
        80, 48, 256, 0, dt_proj_b, 2.f, 1.f, 2, 1, 0, 0, 0, 0, 0, 0);

    // 5) selective scan -> cat cols [0,256)
    scan_kernel<<<64, 256>>>(delta, xc, xdbl, A_log, D_param, cat);

    // 6) qkv = yc @ qkv_w^T              (4096,768)
    gemm_nt<<<dim3(12, 64, 1), blk>>>(yc, qkv_w, qkv, 4096, 768, 256,
        256, 256, 768, 0, nullptr, 0.f, 1.f, 0, 1, 0, 0, 0, 0, 0, 0);

    // 7) S = (Q @ K^T) / sqrt(32), batched over 32 heads (zdiv=8: z = b*8+h)
    gemm_nt<<<dim3(16, 16, 32), blk>>>(qkv, qkv + 256, S, 1024, 1024, 32,
        768, 768, 1024, 0, nullptr, 0.f, 0.17677669529663687f, 0,
        8, 786432LL, 32LL, 786432LL, 32LL, 8388608LL, 1048576LL);

    // 8) softmax over rows of S
    softmax_kernel<<<32768, 128>>>(S);

    // 9) O = P @ V -> o (4096,256)
    attn_out_kernel<<<dim3(16, 32), 256>>>(S, qkv, o);

    // 10) y_att = o @ attn_proj_w^T + b -> cat cols [512,768)
    gemm_nt<<<dim3(4, 64, 1), blk>>>(o, attn_proj_w, cat, 4096, 256, 256,
        256, 256, 768, 512, attn_proj_b, 1.f, 1.f, 1, 1, 0, 0, 0, 0, 0, 0);

    // 11) out = cat @ out_proj_w^T       (4096,768)
    gemm_nt<<<dim3(12, 64, 1), blk>>>(cat, out_proj_w, out, 4096, 768, 768,
        768, 768, 768, 0, nullptr, 0.f, 1.f, 0, 1, 0, 0, 0, 0, 0, 0);
}

// round 3
// speedup vs baseline: 1.5990x; 1.5990x over previous
#include <cuda_runtime.h>
#include <cuda_bf16.h>
#include <math.h>
#include <stdint.h>

// Problem constants: B=4, L=1024, DM=768, DC=256, N=16, R=48, K=4, H=8, HD=32
// M_total = B*L = 4096

// ======================= scratch buffers (static; no allocation) =======================
__device__ float g_xzy[4096 * 768];
__device__ float g_xc[4096 * 256];
__device__ float g_yc[4096 * 256];
__device__ float g_cat[4096 * 768];
__device__ float g_xdbl[4096 * 80];
__device__ float g_delta[4096 * 256];
__device__ float g_qkv[4096 * 768];
__device__ float g_S[32ll * 1024 * 1024];
__device__ float g_o[4096 * 256];

__device__ __nv_bfloat16 g_hsS[4096 * 2304];
__device__ __nv_bfloat16 g_winS[768 * 2304];
__device__ __nv_bfloat16 g_xcS[4096 * 768];
__device__ __nv_bfloat16 g_wxpS[80 * 768];
__device__ __nv_bfloat16 g_dtS[4096 * 144];
__device__ __nv_bfloat16 g_wdtS[256 * 144];
__device__ __nv_bfloat16 g_ycS[4096 * 768];
__device__ __nv_bfloat16 g_wqkvS[768 * 768];
__device__ __nv_bfloat16 g_qS[32 * 1024 * 96];
__device__ __nv_bfloat16 g_kS[32 * 1024 * 96];
__device__ __nv_bfloat16 g_P[32ll * 1024 * 3072];
__device__ __nv_bfloat16 g_vtS[32 * 32 * 3072];
__device__ __nv_bfloat16 g_oS[4096 * 768];
__device__ __nv_bfloat16 g_watS[256 * 768];
__device__ __nv_bfloat16 g_catS[4096 * 2304];
__device__ __nv_bfloat16 g_woutS[768 * 2304];

// ======================= small asm helpers =======================
__device__ __forceinline__ uint32_t smem_to_u32(const void* smem_ptr) {
    uint32_t addr;
    asm("{ .reg .u64 tmp; cvta.to.shared.u64 tmp, %1; cvt.u32.u64 %0, tmp; }"
        : "=r"(addr) : "l"(smem_ptr));
    return addr;
}

__device__ __forceinline__ uint32_t lds32(uint32_t a) {
    uint32_t v;
    asm volatile("ld.shared.b32 %0, [%1];" : "=r"(v) : "r"(a));
    return v;
}

__device__ __forceinline__ void cp16(uint32_t dst, const void* src, bool pred) {
    int sz = pred ? 16 : 0;
    asm volatile("cp.async.cg.shared.global [%0], [%1], 16, %2;"
                 :: "r"(dst), "l"(src), "r"(sz) : "memory");
}

__device__ __forceinline__ void mma16816(float* c, const uint32_t* a, const uint32_t* b) {
    asm volatile(
        "mma.sync.aligned.m16n8k16.row.col.f32.bf16.bf16.f32 "
        "{%0,%1,%2,%3}, {%4,%5,%6,%7}, {%8,%9}, {%0,%1,%2,%3};"
        : "+f"(c[0]), "+f"(c[1]), "+f"(c[2]), "+f"(c[3])
        : "r"(a[0]), "r"(a[1]), "r"(a[2]), "r"(a[3]), "r"(b[0]), "r"(b[1]));
}

// ======================= split-bf16 conversion =======================
// modeA layout along K': [hi, hi, lo]   (left/A operand)
// modeB layout along K': [hi, lo, hi]   (right/B operand)
// => sum over K' = Ah*Bh + Ah*Bl + Al*Bh  (error ~ Al*Bl ~ 2^-16)
__global__ void __launch_bounds__(256) split_kernel(
    const float* __restrict__ src, int ld, long long sz0, long long sz1, int zdiv,
    int M, int K, __nv_bfloat16* __restrict__ dst, int modeB)
{
    int z = blockIdx.y;
    const float* s = src + (long long)(z / zdiv) * sz0 + (long long)(z % zdiv) * sz1;
    __nv_bfloat16* d = dst + (long long)z * M * 3 * K;
    int idx = blockIdx.x * 256 + threadIdx.x;
    if (idx >= M * K) return;
    int m = idx / K, k = idx - m * K;
    float f = s[(long long)m * ld + k];
    __nv_bfloat16 hi = __float2bfloat16(f);
    __nv_bfloat16 lo = __float2bfloat16(f - __bfloat162float(hi));
    __nv_bfloat16* r = d + (long long)m * 3 * K;
    if (modeB) { r[k] = hi; r[K + k] = lo; r[2 * K + k] = hi; }
    else       { r[k] = hi; r[K + k] = hi; r[2 * K + k] = lo; }
}

// V^T split per head: vtS[z][hd][3*1024] (modeB layout)
__global__ void __launch_bounds__(256) vt_split_kernel(
    const float* __restrict__ qkv, __nv_bfloat16* __restrict__ vtS)
{
    int z = blockIdx.y;
    int idx = blockIdx.x * 256 + threadIdx.x;  // hd*1024 + l
    int hd = idx >> 10, l = idx & 1023;
    int b = z >> 3, h = z & 7;
    float f = qkv[((long long)(b * 1024 + l)) * 768 + 512 + h * 32 + hd];
    __nv_bfloat16 hi = __float2bfloat16(f);
    __nv_bfloat16 lo = __float2bfloat16(f - __bfloat162float(hi));
    __nv_bfloat16* r = vtS + (long long)z * 32 * 3072 + (long long)hd * 3072;
    r[l] = hi; r[1024 + l] = lo; r[2048 + l] = hi;
}

// ======================= HMMA bf16 NT GEMM: C = alpha*A@B^T [+epi] =======================
// Tile 128x64x32, 8 warps (4x2), warp tile 32x32, double-buffered cp.async.
// epi: 0 none, 1 +bias*bscale, 2 softplus(v + bias*bscale)
// batching per blockIdx.z: ptr += (z/zdiv)*s?0 + (z%zdiv)*s?1
#define ASTR 80
#define STAGE_BYTES 15360      // 128*80 (A) + 64*80 (B)
__global__ void __launch_bounds__(256) gemm_mma(
    const __nv_bfloat16* __restrict__ A, const __nv_bfloat16* __restrict__ B,
    float* __restrict__ C, int M, int Nglob, int Kp,
    int lda, int ldb, int ldc, int coff,
    const float* __restrict__ bias, float bscale, float alpha, int epi,
    int zdiv, long long sA0, long long sA1, long long sB0, long long sB1,
    long long sC0, long long sC1)
{
    __shared__ __align__(16) char smem[2 * STAGE_BYTES];
    uint32_t sb = smem_to_u32(smem);
    int tid = threadIdx.x;
    int z = blockIdx.z;
    A += (long long)(z / zdiv) * sA0 + (long long)(z % zdiv) * sA1;
    B += (long long)(z / zdiv) * sB0 + (long long)(z % zdiv) * sB1;
    C += (long long)(z / zdiv) * sC0 + (long long)(z % zdiv) * sC1;
    int m0 = blockIdx.y * 128;
    int n0 = blockIdx.x * 64;
    int NC = (Kp + 31) >> 5;

    auto load_stage = [&](int c, int s) {
        int k0 = c * 32;
        uint32_t ab = sb + s * STAGE_BYTES;
        uint32_t bb = ab + 10240;
        #pragma unroll
        for (int i = 0; i < 2; i++) {               // A: 512 16B granules
            int gg = tid + i * 256;
            int r = gg >> 2, c16 = gg & 3;
            int k = k0 + c16 * 8;
            cp16(ab + r * ASTR + c16 * 16, A + (long long)(m0 + r) * lda + k, k < Kp);
        }
        {                                            // B: 256 16B granules
            int r = tid >> 2, c16 = tid & 3;
            int k = k0 + c16 * 8;
            cp16(bb + r * ASTR + c16 * 16, B + (long long)(n0 + r) * ldb + k,
                 (n0 + r) < Nglob && k < Kp);
        }
        asm volatile("cp.async.commit_group;" ::: "memory");
    };

    int wid = tid >> 5, lane = tid & 31;
    int wm = wid & 3, wn = wid >> 2;
    int g = lane >> 2, tg = lane & 3;
    float acc[2][4][4] = {};

    load_stage(0, 0);

    for (int c = 0; c < NC; c++) {
        int s = c & 1;
        if (c + 1 < NC) {
            load_stage(c + 1, s ^ 1);
            asm volatile("cp.async.wait_group 1;" ::: "memory");
        } else {
            asm volatile("cp.async.wait_group 0;" ::: "memory");
        }
        __syncthreads();

        uint32_t ab = sb + s * STAGE_BYTES;
        uint32_t bb = ab + 10240;
        #pragma unroll
        for (int ks = 0; ks < 2; ks++) {
            uint32_t a[2][4], b[4][2];
            #pragma unroll
            for (int mi = 0; mi < 2; mi++) {
                uint32_t base = ab + (wm * 32 + mi * 16 + g) * ASTR + ks * 32 + tg * 4;
                a[mi][0] = lds32(base);
                a[mi][1] = lds32(base + 8 * ASTR);
                a[mi][2] = lds32(base + 16);
                a[mi][3] = lds32(base + 8 * ASTR + 16);
            }
            #pragma unroll
            for (int nj = 0; nj < 4; nj++) {
                uint32_t base = bb + (wn * 32 + nj * 8 + g) * ASTR + ks * 32 + tg * 4;
                b[nj][0] = lds32(base);
                b[nj][1] = lds32(base + 16);
            }
            #pragma unroll
            for (int mi = 0; mi < 2; mi++)
                #pragma unroll
                for (int nj = 0; nj < 4; nj++)
                    mma16816(acc[mi][nj], a[mi], b[nj]);
        }
        __syncthreads();
    }

    // ---- epilogue ----
    #pragma unroll
    for (int mi = 0; mi < 2; mi++) {
        int r0 = m0 + wm * 32 + mi * 16 + g;
        #pragma unroll
        for (int nj = 0; nj < 4; nj++) {
            int cc = n0 + wn * 32 + nj * 8 + tg * 2;
            if (cc >= Nglob) continue;
            #pragma unroll
            for (int hh = 0; hh < 2; hh++) {
                int rr = r0 + hh * 8;
                float v0 = acc[mi][nj][hh * 2 + 0] * alpha;
                float v1 = acc[mi][nj][hh * 2 + 1] * alpha;
                if (epi >= 1) { v0 += bias[cc] * bscale; v1 += bias[cc + 1] * bscale; }
                if (epi == 2) {
                    v0 = (v0 > 15.f) ? v0 : log1pf(__expf(v0));
                    v1 = (v1 > 15.f) ? v1 : log1pf(__expf(v1));
                }
                *(float2*)&C[(long long)rr * ldc + coff + cc] = make_float2(v0, v1);
            }
        }
    }
}

// ======================= depthwise conv (K=4, pad 1/2) + SiLU =======================
__global__ void __launch_bounds__(256) conv_silu_kernel(
    const float* __restrict__ xzy,
    const float* __restrict__ wx, const float* __restrict__ wz, const float* __restrict__ wy,
    float* __restrict__ xc, float* __restrict__ cat, float* __restrict__ yc)
{
    int idx = blockIdx.x * 256 + threadIdx.x;   // m*256 + d
    int d = idx & 255;
    int m = idx >> 8;
    int l = m & 1023;
    const float* base = xzy + (long long)m * 768;
    float a0 = 0.f, a1 = 0.f, a2 = 0.f;
    #pragma unroll
    for (int k = 0; k < 4; k++) {
        int li = l + k - 1;
        if (li < 0 || li >= 1024) continue;
        const float* row = base + (long long)(k - 1) * 768;
        a0 = fmaf(row[d],       wx[d * 4 + k], a0);
        a1 = fmaf(row[256 + d], wz[d * 4 + k], a1);
        a2 = fmaf(row[512 + d], wy[d * 4 + k], a2);
    }
    a0 = a0 / (1.f + __expf(-a0));
    a1 = a1 / (1.f + __expf(-a1));
    a2 = a2 / (1.f + __expf(-a2));
    xc[idx] = a0;
    cat[(long long)m * 768 + 256 + d] = a1;
    yc[idx] = a2;
}

// ======================= selective scan =======================
__global__ void __launch_bounds__(256) scan_kernel(
    const float* __restrict__ delta, const float* __restrict__ xc,
    const float* __restrict__ xdbl, const float* __restrict__ A_log,
    const float* __restrict__ D_param, float* __restrict__ cat)
{
    int t = blockIdx.x * 256 + threadIdx.x;
    int lane = t & 15;
    int p = t >> 4;
    int b = p >> 8;
    int d = p & 255;
    float Acoef = -__expf(A_log[d * 16 + lane]);
    float Dd = D_param[d];
    float h = 0.f;
    const float* dptr = delta + (long long)b * 1024 * 256 + d;
    const float* xptr = xc    + (long long)b * 1024 * 256 + d;
    const float* bptr = xdbl  + (long long)b * 1024 * 80 + 48 + lane;
    const float* cptr = bptr + 16;
    float* optr = cat + (long long)b * 1024 * 768 + d;
    #pragma unroll 4
    for (int l = 0; l < 1024; l++) {
        float dl = dptr[(long long)l * 256];
        float xv = xptr[(long long)l * 256];
        float Bv = bptr[(long long)l * 80];
        float Cv = cptr[(long long)l * 80];
        float dA = __expf(dl * Acoef);
        h = fmaf(dA, h, dl * xv * Bv);
        float yv = h * Cv;
        yv += __shfl_xor_sync(0xffffffffu, yv, 1);
        yv += __shfl_xor_sync(0xffffffffu, yv, 2);
        yv += __shfl_xor_sync(0xffffffffu, yv, 4);
        yv += __shfl_xor_sync(0xffffffffu, yv, 8);
        if (lane == 0) optr[(long long)l * 768] = fmaf(xv, Dd, yv);
    }
}

// ======================= softmax (S fp32 -> split-bf16 P, A-mode) =======================
__global__ void __launch_bounds__(128) softmax_kernel(
    const float* __restrict__ S, __nv_bfloat16* __restrict__ P)
{
    long long row = blockIdx.x;
    const float* p = S + row * 1024;
    __nv_bfloat16* pp = P + row * 3072;
    int t = threadIdx.x;
    float v[8];
    float m = -1e30f;
    #pragma unroll
    for (int i = 0; i < 8; i++) { v[i] = p[t + i * 128]; m = fmaxf(m, v[i]); }
    #pragma unroll
    for (int o = 16; o; o >>= 1) m = fmaxf(m, __shfl_xor_sync(0xffffffffu, m, o));
    __shared__ float red[4], red2[4];
    if ((t & 31) == 0) red[t >> 5] = m;
    __syncthreads();
    m = fmaxf(fmaxf(red[0], red[1]), fmaxf(red[2], red[3]));
    float s = 0.f;
    #pragma unroll
    for (int i = 0; i < 8; i++) { v[i] = __expf(v[i] - m); s += v[i]; }
    #pragma unroll
    for (int o = 16; o; o >>= 1) s += __shfl_xor_sync(0xffffffffu, s, o);
    if ((t & 31) == 0) red2[t >> 5] = s;
    __syncthreads();
    s = red2[0] + red2[1] + red2[2] + red2[3];
    float inv = 1.f / s;
    #pragma unroll
    for (int i = 0; i < 8; i++) {
        float f = v[i] * inv;
        __nv_bfloat16 hi = __float2bfloat16(f);
        __nv_bfloat16 lo = __float2bfloat16(f - __bfloat162float(hi));
        int col = t + i * 128;
        pp[col] = hi; pp[1024 + col] = hi; pp[2048 + col] = lo;
    }
}

// ======================= host launcher =======================
extern "C" void kernel_launch(void* const* d_in, const int* in_sizes, int n_in,
                              void* d_out, int out_size)
{
    const float* hs          = (const float*)d_in[0];
    const float* in_proj_w   = (const float*)d_in[1];
    const float* conv_wx     = (const float*)d_in[2];
    const float* conv_wz     = (const float*)d_in[3];
    const float* conv_wy     = (const float*)d_in[4];
    const float* x_proj_w    = (const float*)d_in[5];
    const float* dt_proj_w   = (const float*)d_in[6];
    const float* dt_proj_b   = (const float*)d_in[7];
    const float* A_log       = (const float*)d_in[8];
    const float* D_param     = (const float*)d_in[9];
    const float* out_proj_w  = (const float*)d_in[10];
    const float* qkv_w       = (const float*)d_in[11];
    const float* attn_proj_w = (const float*)d_in[12];
    const float* attn_proj_b = (const float*)d_in[13];
    float* out = (float*)d_out;

    float *xzy, *xc, *yc, *cat, *xdbl, *delta, *qkv, *S, *o;
    cudaGetSymbolAddress((void**)&xzy,   g_xzy);
    cudaGetSymbolAddress((void**)&xc,    g_xc);
    cudaGetSymbolAddress((void**)&yc,    g_yc);
    cudaGetSymbolAddress((void**)&cat,   g_cat);
    cudaGetSymbolAddress((void**)&xdbl,  g_xdbl);
    cudaGetSymbolAddress((void**)&delta, g_delta);
    cudaGetSymbolAddress((void**)&qkv,   g_qkv);
    cudaGetSymbolAddress((void**)&S,     g_S);
    cudaGetSymbolAddress((void**)&o,     g_o);

    __nv_bfloat16 *hsS, *winS, *xcS, *wxpS, *dtS, *wdtS, *ycS, *wqkvS;
    __nv_bfloat16 *qSb, *kSb, *Pb, *vtS, *oS, *watS, *catS, *woutS;
    cudaGetSymbolAddress((void**)&hsS,   g_hsS);
    cudaGetSymbolAddress((void**)&winS,  g_winS);
    cudaGetSymbolAddress((void**)&xcS,   g_xcS);
    cudaGetSymbolAddress((void**)&wxpS,  g_wxpS);
    cudaGetSymbolAddress((void**)&dtS,   g_dtS);
    cudaGetSymbolAddress((void**)&wdtS,  g_wdtS);
    cudaGetSymbolAddress((void**)&ycS,   g_ycS);
    cudaGetSymbolAddress((void**)&wqkvS, g_wqkvS);
    cudaGetSymbolAddress((void**)&qSb,   g_qS);
    cudaGetSymbolAddress((void**)&kSb,   g_kS);
    cudaGetSymbolAddress((void**)&Pb,    g_P);
    cudaGetSymbolAddress((void**)&vtS,   g_vtS);
    cudaGetSymbolAddress((void**)&oS,    g_oS);
    cudaGetSymbolAddress((void**)&watS,  g_watS);
    cudaGetSymbolAddress((void**)&catS,  g_catS);
    cudaGetSymbolAddress((void**)&woutS, g_woutS);

    // 1) in_proj: xzy = hs @ in_proj_w^T   (4096x768, K=768 -> Kp=2304)
    split_kernel<<<dim3(12288, 1), 256>>>(hs, 768, 0, 0, 1, 4096, 768, hsS, 0);
    split_kernel<<<dim3(2304, 1), 256>>>(in_proj_w, 768, 0, 0, 1, 768, 768, winS, 1);
    gemm_mma<<<dim3(12, 32, 1), 256>>>(hsS, winS, xzy, 4096, 768, 2304,
        2304, 2304, 768, 0, nullptr, 0.f, 1.f, 0, 1, 0, 0, 0, 0, 0, 0);

    // 2) depthwise conv + SiLU
    conv_silu_kernel<<<4096, 256>>>(xzy, conv_wx, conv_wz, conv_wy, xc, cat, yc);

    // 3) x_dbl = xc @ x_proj_w^T   (4096x80, K=256 -> 768)
    split_kernel<<<dim3(4096, 1), 256>>>(xc, 256, 0, 0, 1, 4096, 256, xcS, 0);
    split_kernel<<<dim3(80, 1), 256>>>(x_proj_w, 256, 0, 0, 1, 80, 256, wxpS, 1);
    gemm_mma<<<dim3(2, 32, 1), 256>>>(xcS, wxpS, xdbl, 4096, 80, 768,
        768, 768, 80, 0, nullptr, 0.f, 1.f, 0, 1, 0, 0, 0, 0, 0, 0);

    // 4) delta = softplus(dt @ dt_proj_w^T + 2*dt_proj_b)   (K=48 -> 144)
    split_kernel<<<dim3(768, 1), 256>>>(xdbl, 80, 0, 0, 1, 4096, 48, dtS, 0);
    split_kernel<<<dim3(48, 1), 256>>>(dt_proj_w, 48, 0, 0, 1, 256, 48, wdtS, 1);
    gemm_mma<<<dim3(4, 32, 1), 256>>>(dtS, wdtS, delta, 4096, 256, 144,
        144, 144, 256, 0, dt_proj_b, 2.f, 1.f, 2, 1, 0, 0, 0, 0, 0, 0);

    // 5) selective scan -> cat cols [0,256)
    scan_kernel<<<64, 256>>>(delta, xc, xdbl, A_log, D_param, cat);

    // 6) qkv = yc @ qkv_w^T   (4096x768, K=256 -> 768)
    split_kernel<<<dim3(4096, 1), 256>>>(yc, 256, 0, 0, 1, 4096, 256, ycS, 0);
    split_kernel<<<dim3(768, 1), 256>>>(qkv_w, 256, 0, 0, 1, 768, 256, wqkvS, 1);
    gemm_mma<<<dim3(12, 32, 1), 256>>>(ycS, wqkvS, qkv, 4096, 768, 768,
        768, 768, 768, 0, nullptr, 0.f, 1.f, 0, 1, 0, 0, 0, 0, 0, 0);

    // 7) per-head Q/K split layouts (K=32 -> 96), z = b*8+h
    split_kernel<<<dim3(128, 32), 256>>>(qkv, 768, 786432, 32, 8, 1024, 32, qSb, 0);
    split_kernel<<<dim3(128, 32), 256>>>(qkv + 256, 768, 786432, 32, 8, 1024, 32, kSb, 1);

    // 8) S = (Q @ K^T) * HD^-0.5 per head
    gemm_mma<<<dim3(16, 8, 32), 256>>>(qSb, kSb, S, 1024, 1024, 96,
        96, 96, 1024, 0, nullptr, 0.f, 0.17677669529663687f, 0,
        1, 98304, 0, 98304, 0, 1048576, 0);

    // 9) softmax rows -> split-bf16 P
    softmax_kernel<<<32768, 128>>>(S, Pb);

    // 10) V^T split per head
    vt_split_kernel<<<dim3(128, 32), 256>>>(qkv, vtS);

    // 11) O = P @ V   (per head M=1024, N=32, Kp=3072) -> o (4096x256)
    gemm_mma<<<dim3(1, 8, 32), 256>>>(Pb, vtS, o, 1024, 32, 3072,
        3072, 3072, 256, 0, nullptr, 0.f, 1.f, 0,
        8, 25165824, 3145728, 786432, 98304, 262144, 32);

    // 12) y_att = o @ attn_proj_w^T + b -> cat cols [512,768)
    split_kernel<<<dim3(4096, 1), 256>>>(o, 256, 0, 0, 1, 4096, 256, oS, 0);
    split_kernel<<<dim3(256, 1), 256>>>(attn_proj_w, 256, 0, 0, 1, 256, 256, watS, 1);
    gemm_mma<<<dim3(4, 32, 1), 256>>>(oS, watS, cat, 4096, 256, 768,
        768, 768, 768, 512, attn_proj_b, 1.f, 1.f, 1, 1, 0, 0, 0, 0, 0, 0);

    // 13) out = cat @ out_proj_w^T   (K=768 -> 2304)
    split_kernel<<<dim3(12288, 1), 256>>>(cat, 768, 0, 0, 1, 4096, 768, catS, 0);
    split_kernel<<<dim3(2304, 1), 256>>>(out_proj_w, 768, 0, 0, 1, 768, 768, woutS, 1);
    gemm_mma<<<dim3(12, 32, 1), 256>>>(catS, woutS, out, 4096, 768, 2304,
        2304, 2304, 768, 0, nullptr, 0.f, 1.f, 0, 1, 0, 0, 0, 0, 0, 0);
}

// round 4
// speedup vs baseline: 1.9674x; 1.2304x over previous
#include <cuda_runtime.h>
#include <cuda_bf16.h>
#include <math.h>
#include <stdint.h>

// Problem constants: B=4, L=1024, DM=768, DC=256, N=16, R=48, K=4, H=8, HD=32
// M_total = B*L = 4096

// ======================= scratch buffers (static; no allocation) =======================
__device__ float g_xzy[4096 * 768];
__device__ float g_xc[4096 * 256];
__device__ float g_yc[4096 * 256];
__device__ float g_cat[4096 * 768];
__device__ float g_xdbl[4096 * 80];
__device__ float g_delta[4096 * 256];
__device__ float g_qkv[4096 * 768];
__device__ float g_o[4096 * 256];

__device__ __nv_bfloat16 g_hsS[4096 * 2304];
__device__ __nv_bfloat16 g_winS[768 * 2304];
__device__ __nv_bfloat16 g_xcS[4096 * 768];
__device__ __nv_bfloat16 g_wxpS[80 * 768];
__device__ __nv_bfloat16 g_dtS[4096 * 144];
__device__ __nv_bfloat16 g_wdtS[256 * 144];
__device__ __nv_bfloat16 g_ycS[4096 * 768];
__device__ __nv_bfloat16 g_wqkvS[768 * 768];
__device__ __nv_bfloat16 g_oS[4096 * 768];
__device__ __nv_bfloat16 g_watS[256 * 768];
__device__ __nv_bfloat16 g_catS[4096 * 2304];
__device__ __nv_bfloat16 g_woutS[768 * 2304];

// ======================= small asm helpers =======================
__device__ __forceinline__ uint32_t smem_to_u32(const void* smem_ptr) {
    uint32_t addr;
    asm("{ .reg .u64 tmp; cvta.to.shared.u64 tmp, %1; cvt.u32.u64 %0, tmp; }"
        : "=r"(addr) : "l"(smem_ptr));
    return addr;
}

__device__ __forceinline__ uint32_t lds32(uint32_t a) {
    uint32_t v;
    asm volatile("ld.shared.b32 %0, [%1];" : "=r"(v) : "r"(a));
    return v;
}

__device__ __forceinline__ void cp16(uint32_t dst, const void* src, bool pred) {
    int sz = pred ? 16 : 0;
    asm volatile("cp.async.cg.shared.global [%0], [%1], 16, %2;"
                 :: "r"(dst), "l"(src), "r"(sz) : "memory");
}

__device__ __forceinline__ void mma16816(float* c, const uint32_t* a, const uint32_t* b) {
    asm volatile(
        "mma.sync.aligned.m16n8k16.row.col.f32.bf16.bf16.f32 "
        "{%0,%1,%2,%3}, {%4,%5,%6,%7}, {%8,%9}, {%0,%1,%2,%3};"
        : "+f"(c[0]), "+f"(c[1]), "+f"(c[2]), "+f"(c[3])
        : "r"(a[0]), "r"(a[1]), "r"(a[2]), "r"(a[3]), "r"(b[0]), "r"(b[1]));
}

__device__ __forceinline__ uint32_t packh(float x, float y) {
    __nv_bfloat162 t = __floats2bfloat162_rn(x, y);
    return *(uint32_t*)&t;
}

// ======================= split-bf16 conversion =======================
// modeA layout along K': [hi, hi, lo]   (left/A operand)
// modeB layout along K': [hi, lo, hi]   (right/B operand)
__global__ void __launch_bounds__(256) split_kernel(
    const float* __restrict__ src, int ld, long long sz0, long long sz1, int zdiv,
    int M, int K, __nv_bfloat16* __restrict__ dst, int modeB)
{
    int z = blockIdx.y;
    const float* s = src + (long long)(z / zdiv) * sz0 + (long long)(z % zdiv) * sz1;
    __nv_bfloat16* d = dst + (long long)z * M * 3 * K;
    int idx = blockIdx.x * 256 + threadIdx.x;
    if (idx >= M * K) return;
    int m = idx / K, k = idx - m * K;
    float f = s[(long long)m * ld + k];
    __nv_bfloat16 hi = __float2bfloat16(f);
    __nv_bfloat16 lo = __float2bfloat16(f - __bfloat162float(hi));
    __nv_bfloat16* r = d + (long long)m * 3 * K;
    if (modeB) { r[k] = hi; r[K + k] = lo; r[2 * K + k] = hi; }
    else       { r[k] = hi; r[K + k] = hi; r[2 * K + k] = lo; }
}

// ======================= HMMA bf16 NT GEMM (unchanged from round 3) =======================
#define ASTR 80
#define STAGE_BYTES 15360
__global__ void __launch_bounds__(256) gemm_mma(
    const __nv_bfloat16* __restrict__ A, const __nv_bfloat16* __restrict__ B,
    float* __restrict__ C, int M, int Nglob, int Kp,
    int lda, int ldb, int ldc, int coff,
    const float* __restrict__ bias, float bscale, float alpha, int epi,
    int zdiv, long long sA0, long long sA1, long long sB0, long long sB1,
    long long sC0, long long sC1)
{
    __shared__ __align__(16) char smem[2 * STAGE_BYTES];
    uint32_t sb = smem_to_u32(smem);
    int tid = threadIdx.x;
    int z = blockIdx.z;
    A += (long long)(z / zdiv) * sA0 + (long long)(z % zdiv) * sA1;
    B += (long long)(z / zdiv) * sB0 + (long long)(z % zdiv) * sB1;
    C += (long long)(z / zdiv) * sC0 + (long long)(z % zdiv) * sC1;
    int m0 = blockIdx.y * 128;
    int n0 = blockIdx.x * 64;
    int NC = (Kp + 31) >> 5;

    auto load_stage = [&](int c, int s) {
        int k0 = c * 32;
        uint32_t ab = sb + s * STAGE_BYTES;
        uint32_t bb = ab + 10240;
        #pragma unroll
        for (int i = 0; i < 2; i++) {
            int gg = tid + i * 256;
            int r = gg >> 2, c16 = gg & 3;
            int k = k0 + c16 * 8;
            cp16(ab + r * ASTR + c16 * 16, A + (long long)(m0 + r) * lda + k, k < Kp);
        }
        {
            int r = tid >> 2, c16 = tid & 3;
            int k = k0 + c16 * 8;
            cp16(bb + r * ASTR + c16 * 16, B + (long long)(n0 + r) * ldb + k,
                 (n0 + r) < Nglob && k < Kp);
        }
        asm volatile("cp.async.commit_group;" ::: "memory");
    };

    int wid = tid >> 5, lane = tid & 31;
    int wm = wid & 3, wn = wid >> 2;
    int g = lane >> 2, tg = lane & 3;
    float acc[2][4][4] = {};

    load_stage(0, 0);

    for (int c = 0; c < NC; c++) {
        int s = c & 1;
        if (c + 1 < NC) {
            load_stage(c + 1, s ^ 1);
            asm volatile("cp.async.wait_group 1;" ::: "memory");
        } else {
            asm volatile("cp.async.wait_group 0;" ::: "memory");
        }
        __syncthreads();

        uint32_t ab = sb + s * STAGE_BYTES;
        uint32_t bb = ab + 10240;
        #pragma unroll
        for (int ks = 0; ks < 2; ks++) {
            uint32_t a[2][4], b[4][2];
            #pragma unroll
            for (int mi = 0; mi < 2; mi++) {
                uint32_t base = ab + (wm * 32 + mi * 16 + g) * ASTR + ks * 32 + tg * 4;
                a[mi][0] = lds32(base);
                a[mi][1] = lds32(base + 8 * ASTR);
                a[mi][2] = lds32(base + 16);
                a[mi][3] = lds32(base + 8 * ASTR + 16);
            }
            #pragma unroll
            for (int nj = 0; nj < 4; nj++) {
                uint32_t base = bb + (wn * 32 + nj * 8 + g) * ASTR + ks * 32 + tg * 4;
                b[nj][0] = lds32(base);
                b[nj][1] = lds32(base + 16);
            }
            #pragma unroll
            for (int mi = 0; mi < 2; mi++)
                #pragma unroll
                for (int nj = 0; nj < 4; nj++)
                    mma16816(acc[mi][nj], a[mi], b[nj]);
        }
        __syncthreads();
    }

    #pragma unroll
    for (int mi = 0; mi < 2; mi++) {
        int r0 = m0 + wm * 32 + mi * 16 + g;
        #pragma unroll
        for (int nj = 0; nj < 4; nj++) {
            int cc = n0 + wn * 32 + nj * 8 + tg * 2;
            if (cc >= Nglob) continue;
            #pragma unroll
            for (int hh = 0; hh < 2; hh++) {
                int rr = r0 + hh * 8;
                float v0 = acc[mi][nj][hh * 2 + 0] * alpha;
                float v1 = acc[mi][nj][hh * 2 + 1] * alpha;
                if (epi >= 1) { v0 += bias[cc] * bscale; v1 += bias[cc + 1] * bscale; }
                if (epi == 2) {
                    v0 = (v0 > 15.f) ? v0 : log1pf(__expf(v0));
                    v1 = (v1 > 15.f) ? v1 : log1pf(__expf(v1));
                }
                *(float2*)&C[(long long)rr * ldc + coff + cc] = make_float2(v0, v1);
            }
        }
    }
}

// ======================= fused flash attention =======================
// grid (8 qtiles, 32 heads), 256 threads. Q tile 128 rows, K tiles 128 keys.
// Split-bf16 throughout: QK^T exact-ish via [hi,hi,lo]x[hi,lo,hi]; PV via
// 3 passes Ph*Vh + Ph*Vl + Pl*Vh with P fragments built in-register from S accums.
#define SQ 208      // 96 bf16 = 192B + 16 pad  (52 words; 20g+tg conflict-free)
#define SV 272      // 128 bf16 = 256B + 16 pad
#define OFF_VTH 26624
#define OFF_VTL 35328
#define OFF_RMAX 44032
#define OFF_RSUM 45056
__global__ void __launch_bounds__(256, 1) flash_kernel(
    const float* __restrict__ qkv, float* __restrict__ obuf)
{
    __shared__ __align__(16) char smem[46080];
    uint32_t sb = smem_to_u32(smem);
    float* rmax = (float*)(smem + OFF_RMAX);   // [2][128]
    float* rsum = (float*)(smem + OFF_RSUM);   // [2][128]
    int tid = threadIdx.x;
    int wid = tid >> 5, lane = tid & 31;
    int wm = wid & 3, wn = wid >> 2;
    int g = lane >> 2, tg = lane & 3;
    int z = blockIdx.y;
    int b = z >> 3, h = z & 7;
    int q0 = blockIdx.x * 128;
    const float alpha = 0.17677669529663687f;   // HD^-0.5
    const float* qkvb = qkv + (long long)b * 1024 * 768 + h * 32;

    // ---- stage Q (pre-scaled by alpha) split modeA into ks region ----
    #pragma unroll
    for (int j = 0; j < 16; j++) {
        int i = tid + j * 256;
        int row = i >> 5, d = i & 31;
        float f = qkvb[(long long)(q0 + row) * 768 + d] * alpha;
        __nv_bfloat16 hi = __float2bfloat16(f);
        __nv_bfloat16 lo = __float2bfloat16(f - __bfloat162float(hi));
        *(__nv_bfloat16*)(smem + row * SQ + d * 2) = hi;
        *(__nv_bfloat16*)(smem + row * SQ + 64 + d * 2) = hi;
        *(__nv_bfloat16*)(smem + row * SQ + 128 + d * 2) = lo;
    }
    __syncthreads();
    // ---- Q A-frags to registers (persistent) ----
    uint32_t qa[6][2][4];
    #pragma unroll
    for (int kb = 0; kb < 6; kb++)
        #pragma unroll
        for (int mi = 0; mi < 2; mi++) {
            uint32_t base = sb + (wm * 32 + mi * 16 + g) * SQ + kb * 32 + tg * 4;
            qa[kb][mi][0] = lds32(base);
            qa[kb][mi][1] = lds32(base + 8 * SQ);
            qa[kb][mi][2] = lds32(base + 16);
            qa[kb][mi][3] = lds32(base + 8 * SQ + 16);
        }

    float accO[2][4][4] = {};
    float m_run[2][2] = {{-1e30f, -1e30f}, {-1e30f, -1e30f}};
    float l_run[2][2] = {{0.f, 0.f}, {0.f, 0.f}};

    for (int t = 0; t < 8; t++) {
        int j0 = t * 128;
        __syncthreads();      // ks / v reuse safe (Q frags already in regs)
        // ---- load K (split modeB into ks) and V (hi/lo transposed) ----
        #pragma unroll
        for (int j = 0; j < 16; j++) {
            int i = tid + j * 256;
            int key = i >> 5, d = i & 31;
            const float* src = qkvb + (long long)(j0 + key) * 768;
            float kf = src[256 + d];
            __nv_bfloat16 khi = __float2bfloat16(kf);
            __nv_bfloat16 klo = __float2bfloat16(kf - __bfloat162float(khi));
            *(__nv_bfloat16*)(smem + key * SQ + d * 2) = khi;
            *(__nv_bfloat16*)(smem + key * SQ + 64 + d * 2) = klo;
            *(__nv_bfloat16*)(smem + key * SQ + 128 + d * 2) = khi;
            float vf = src[512 + d];
            __nv_bfloat16 vhi = __float2bfloat16(vf);
            __nv_bfloat16 vlo = __float2bfloat16(vf - __bfloat162float(vhi));
            *(__nv_bfloat16*)(smem + OFF_VTH + d * SV + key * 2) = vhi;
            *(__nv_bfloat16*)(smem + OFF_VTL + d * SV + key * 2) = vlo;
        }
        __syncthreads();

        // ---- S = Q @ K^T (warp: rows wm*32..+32, cols wn*64..+64) ----
        float accS[2][8][4] = {};
        #pragma unroll
        for (int kb = 0; kb < 6; kb++) {
            uint32_t bfr[8][2];
            #pragma unroll
            for (int nj = 0; nj < 8; nj++) {
                uint32_t base = sb + (wn * 64 + nj * 8 + g) * SQ + kb * 32 + tg * 4;
                bfr[nj][0] = lds32(base);
                bfr[nj][1] = lds32(base + 16);
            }
            #pragma unroll
            for (int mi = 0; mi < 2; mi++)
                #pragma unroll
                for (int nj = 0; nj < 8; nj++)
                    mma16816(accS[mi][nj], qa[kb][mi], bfr[nj]);
        }

        // ---- row max (quad + cross-warp-pair) ----
        float mx[2][2];
        #pragma unroll
        for (int mi = 0; mi < 2; mi++)
            #pragma unroll
            for (int hh = 0; hh < 2; hh++) {
                float m = -1e30f;
                #pragma unroll
                for (int nj = 0; nj < 8; nj++)
                    m = fmaxf(m, fmaxf(accS[mi][nj][hh * 2], accS[mi][nj][hh * 2 + 1]));
                m = fmaxf(m, __shfl_xor_sync(0xffffffffu, m, 1));
                m = fmaxf(m, __shfl_xor_sync(0xffffffffu, m, 2));
                mx[mi][hh] = m;
            }
        if (tg == 0) {
            #pragma unroll
            for (int mi = 0; mi < 2; mi++)
                #pragma unroll
                for (int hh = 0; hh < 2; hh++)
                    rmax[wn * 128 + wm * 32 + mi * 16 + hh * 8 + g] = mx[mi][hh];
        }
        __syncthreads();

        float fsc[2][2], mnew[2][2], ls[2][2];
        #pragma unroll
        for (int mi = 0; mi < 2; mi++)
            #pragma unroll
            for (int hh = 0; hh < 2; hh++) {
                int r = wm * 32 + mi * 16 + hh * 8 + g;
                float tm = fmaxf(rmax[r], rmax[128 + r]);
                float mn = fmaxf(m_run[mi][hh], tm);
                mnew[mi][hh] = mn;
                fsc[mi][hh] = __expf(m_run[mi][hh] - mn);
                ls[mi][hh] = 0.f;
            }
        // exp in place, local sums, scale accO
        #pragma unroll
        for (int mi = 0; mi < 2; mi++)
            #pragma unroll
            for (int hh = 0; hh < 2; hh++) {
                float mn = mnew[mi][hh];
                float s = 0.f;
                #pragma unroll
                for (int nj = 0; nj < 8; nj++) {
                    float p0 = __expf(accS[mi][nj][hh * 2] - mn);
                    float p1 = __expf(accS[mi][nj][hh * 2 + 1] - mn);
                    accS[mi][nj][hh * 2] = p0;
                    accS[mi][nj][hh * 2 + 1] = p1;
                    s += p0 + p1;
                }
                ls[mi][hh] = s;
                float f = fsc[mi][hh];
                #pragma unroll
                for (int nj2 = 0; nj2 < 4; nj2++) {
                    accO[mi][nj2][hh * 2] *= f;
                    accO[mi][nj2][hh * 2 + 1] *= f;
                }
            }
        #pragma unroll
        for (int mi = 0; mi < 2; mi++)
            #pragma unroll
            for (int hh = 0; hh < 2; hh++) {
                float s = ls[mi][hh];
                s += __shfl_xor_sync(0xffffffffu, s, 1);
                s += __shfl_xor_sync(0xffffffffu, s, 2);
                ls[mi][hh] = s;
            }
        if (tg == 0) {
            #pragma unroll
            for (int mi = 0; mi < 2; mi++)
                #pragma unroll
                for (int hh = 0; hh < 2; hh++)
                    rsum[wn * 128 + wm * 32 + mi * 16 + hh * 8 + g] = ls[mi][hh];
        }
        __syncthreads();
        #pragma unroll
        for (int mi = 0; mi < 2; mi++)
            #pragma unroll
            for (int hh = 0; hh < 2; hh++) {
                int r = wm * 32 + mi * 16 + hh * 8 + g;
                l_run[mi][hh] = l_run[mi][hh] * fsc[mi][hh] + rsum[r] + rsum[128 + r];
                m_run[mi][hh] = mnew[mi][hh];
            }

        // ---- O += P @ V  (warp's 64 keys; 3 split passes) ----
        #pragma unroll
        for (int kb = 0; kb < 4; kb++) {
            uint32_t pah[2][4], pal[2][4];
            #pragma unroll
            for (int mi = 0; mi < 2; mi++) {
                float x0 = accS[mi][2 * kb][0], x1 = accS[mi][2 * kb][1];
                float x2 = accS[mi][2 * kb][2], x3 = accS[mi][2 * kb][3];
                float y0 = accS[mi][2 * kb + 1][0], y1 = accS[mi][2 * kb + 1][1];
                float y2 = accS[mi][2 * kb + 1][2], y3 = accS[mi][2 * kb + 1][3];
                pah[mi][0] = packh(x0, x1);
                pah[mi][1] = packh(x2, x3);
                pah[mi][2] = packh(y0, y1);
                pah[mi][3] = packh(y2, y3);
                __nv_bfloat162 t0 = *(__nv_bfloat162*)&pah[mi][0];
                __nv_bfloat162 t1 = *(__nv_bfloat162*)&pah[mi][1];
                __nv_bfloat162 t2 = *(__nv_bfloat162*)&pah[mi][2];
                __nv_bfloat162 t3 = *(__nv_bfloat162*)&pah[mi][3];
                pal[mi][0] = packh(x0 - __bfloat162float(t0.x), x1 - __bfloat162float(t0.y));
                pal[mi][1] = packh(x2 - __bfloat162float(t1.x), x3 - __bfloat162float(t1.y));
                pal[mi][2] = packh(y0 - __bfloat162float(t2.x), y1 - __bfloat162float(t2.y));
                pal[mi][3] = packh(y2 - __bfloat162float(t3.x), y3 - __bfloat162float(t3.y));
            }
            uint32_t vbh[4][2], vbl[4][2];
            int kcol = (wn * 64 + kb * 16 + tg * 2) * 2;
            #pragma unroll
            for (int nj2 = 0; nj2 < 4; nj2++) {
                uint32_t bh = sb + OFF_VTH + (nj2 * 8 + g) * SV + kcol;
                uint32_t bl = sb + OFF_VTL + (nj2 * 8 + g) * SV + kcol;
                vbh[nj2][0] = lds32(bh);  vbh[nj2][1] = lds32(bh + 16);
                vbl[nj2][0] = lds32(bl);  vbl[nj2][1] = lds32(bl + 16);
            }
            #pragma unroll
            for (int mi = 0; mi < 2; mi++)
                #pragma unroll
                for (int nj2 = 0; nj2 < 4; nj2++) {
                    mma16816(accO[mi][nj2], pah[mi], vbh[nj2]);
                    mma16816(accO[mi][nj2], pah[mi], vbl[nj2]);
                    mma16816(accO[mi][nj2], pal[mi], vbh[nj2]);
                }
        }
    }

    // ---- cross-warp O reduction + normalize + store ----
    __syncthreads();
    float* Ob = (float*)smem;   // [128][36] overlays ks
    if (wn == 0) {
        #pragma unroll
        for (int mi = 0; mi < 2; mi++)
            #pragma unroll
            for (int hh = 0; hh < 2; hh++) {
                int r = wm * 32 + mi * 16 + hh * 8 + g;
                #pragma unroll
                for (int nj2 = 0; nj2 < 4; nj2++) {
                    Ob[r * 36 + nj2 * 8 + tg * 2]     = accO[mi][nj2][hh * 2];
                    Ob[r * 36 + nj2 * 8 + tg * 2 + 1] = accO[mi][nj2][hh * 2 + 1];
                }
            }
    }
    __syncthreads();
    if (wn == 1) {
        #pragma unroll
        for (int mi = 0; mi < 2; mi++)
            #pragma unroll
            for (int hh = 0; hh < 2; hh++) {
                int r = wm * 32 + mi * 16 + hh * 8 + g;
                float inv = 1.f / l_run[mi][hh];
                #pragma unroll
                for (int nj2 = 0; nj2 < 4; nj2++) {
                    int d = nj2 * 8 + tg * 2;
                    float v0 = (Ob[r * 36 + d]     + accO[mi][nj2][hh * 2])     * inv;
                    float v1 = (Ob[r * 36 + d + 1] + accO[mi][nj2][hh * 2 + 1]) * inv;
                    *(float2*)&obuf[(long long)(b * 1024 + q0 + r) * 256 + h * 32 + d] =
                        make_float2(v0, v1);
                }
            }
    }
}

// ======================= depthwise conv (K=4, pad 1/2) + SiLU =======================
__global__ void __launch_bounds__(256) conv_silu_kernel(
    const float* __restrict__ xzy,
    const float* __restrict__ wx, const float* __restrict__ wz, const float* __restrict__ wy,
    float* __restrict__ xc, float* __restrict__ cat, float* __restrict__ yc)
{
    int idx = blockIdx.x * 256 + threadIdx.x;
    int d = idx & 255;
    int m = idx >> 8;
    int l = m & 1023;
    const float* base = xzy + (long long)m * 768;
    float a0 = 0.f, a1 = 0.f, a2 = 0.f;
    #pragma unroll
    for (int k = 0; k < 4; k++) {
        int li = l + k - 1;
        if (li < 0 || li >= 1024) continue;
        const float* row = base + (long long)(k - 1) * 768;
        a0 = fmaf(row[d],       wx[d * 4 + k], a0);
        a1 = fmaf(row[256 + d], wz[d * 4 + k], a1);
        a2 = fmaf(row[512 + d], wy[d * 4 + k], a2);
    }
    a0 = a0 / (1.f + __expf(-a0));
    a1 = a1 / (1.f + __expf(-a1));
    a2 = a2 / (1.f + __expf(-a2));
    xc[idx] = a0;
    cat[(long long)m * 768 + 256 + d] = a1;
    yc[idx] = a2;
}

// ======================= selective scan =======================
__global__ void __launch_bounds__(256) scan_kernel(
    const float* __restrict__ delta, const float* __restrict__ xc,
    const float* __restrict__ xdbl, const float* __restrict__ A_log,
    const float* __restrict__ D_param, float* __restrict__ cat)
{
    int t = blockIdx.x * 256 + threadIdx.x;
    int lane = t & 15;
    int p = t >> 4;
    int b = p >> 8;
    int d = p & 255;
    float Acoef = -__expf(A_log[d * 16 + lane]);
    float Dd = D_param[d];
    float h = 0.f;
    const float* dptr = delta + (long long)b * 1024 * 256 + d;
    const float* xptr = xc    + (long long)b * 1024 * 256 + d;
    const float* bptr = xdbl  + (long long)b * 1024 * 80 + 48 + lane;
    const float* cptr = bptr + 16;
    float* optr = cat + (long long)b * 1024 * 768 + d;
    #pragma unroll 4
    for (int l = 0; l < 1024; l++) {
        float dl = dptr[(long long)l * 256];
        float xv = xptr[(long long)l * 256];
        float Bv = bptr[(long long)l * 80];
        float Cv = cptr[(long long)l * 80];
        float dA = __expf(dl * Acoef);
        h = fmaf(dA, h, dl * xv * Bv);
        float yv = h * Cv;
        yv += __shfl_xor_sync(0xffffffffu, yv, 1);
        yv += __shfl_xor_sync(0xffffffffu, yv, 2);
        yv += __shfl_xor_sync(0xffffffffu, yv, 4);
        yv += __shfl_xor_sync(0xffffffffu, yv, 8);
        if (lane == 0) optr[(long long)l * 768] = fmaf(xv, Dd, yv);
    }
}

// ======================= host launcher =======================
extern "C" void kernel_launch(void* const* d_in, const int* in_sizes, int n_in,
                              void* d_out, int out_size)
{
    const float* hs          = (const float*)d_in[0];
    const float* in_proj_w   = (const float*)d_in[1];
    const float* conv_wx     = (const float*)d_in[2];
    const float* conv_wz     = (const float*)d_in[3];
    const float* conv_wy     = (const float*)d_in[4];
    const float* x_proj_w    = (const float*)d_in[5];
    const float* dt_proj_w   = (const float*)d_in[6];
    const float* dt_proj_b   = (const float*)d_in[7];
    const float* A_log       = (const float*)d_in[8];
    const float* D_param     = (const float*)d_in[9];
    const float* out_proj_w  = (const float*)d_in[10];
    const float* qkv_w       = (const float*)d_in[11];
    const float* attn_proj_w = (const float*)d_in[12];
    const float* attn_proj_b = (const float*)d_in[13];
    float* out = (float*)d_out;

    float *xzy, *xc, *yc, *cat, *xdbl, *delta, *qkv, *o;
    cudaGetSymbolAddress((void**)&xzy,   g_xzy);
    cudaGetSymbolAddress((void**)&xc,    g_xc);
    cudaGetSymbolAddress((void**)&yc,    g_yc);
    cudaGetSymbolAddress((void**)&cat,   g_cat);
    cudaGetSymbolAddress((void**)&xdbl,  g_xdbl);
    cudaGetSymbolAddress((void**)&delta, g_delta);
    cudaGetSymbolAddress((void**)&qkv,   g_qkv);
    cudaGetSymbolAddress((void**)&o,     g_o);

    __nv_bfloat16 *hsS, *winS, *xcS, *wxpS, *dtS, *wdtS, *ycS, *wqkvS;
    __nv_bfloat16 *oS, *watS, *catS, *woutS;
    cudaGetSymbolAddress((void**)&hsS,   g_hsS);
    cudaGetSymbolAddress((void**)&winS,  g_winS);
    cudaGetSymbolAddress((void**)&xcS,   g_xcS);
    cudaGetSymbolAddress((void**)&wxpS,  g_wxpS);
    cudaGetSymbolAddress((void**)&dtS,   g_dtS);
    cudaGetSymbolAddress((void**)&wdtS,  g_wdtS);
    cudaGetSymbolAddress((void**)&ycS,   g_ycS);
    cudaGetSymbolAddress((void**)&wqkvS, g_wqkvS);
    cudaGetSymbolAddress((void**)&oS,    g_oS);
    cudaGetSymbolAddress((void**)&watS,  g_watS);
    cudaGetSymbolAddress((void**)&catS,  g_catS);
    cudaGetSymbolAddress((void**)&woutS, g_woutS);

    // 1) in_proj: xzy = hs @ in_proj_w^T   (4096x768, Kp=2304)
    split_kernel<<<dim3(12288, 1), 256>>>(hs, 768, 0, 0, 1, 4096, 768, hsS, 0);
    split_kernel<<<dim3(2304, 1), 256>>>(in_proj_w, 768, 0, 0, 1, 768, 768, winS, 1);
    gemm_mma<<<dim3(12, 32, 1), 256>>>(hsS, winS, xzy, 4096, 768, 2304,
        2304, 2304, 768, 0, nullptr, 0.f, 1.f, 0, 1, 0, 0, 0, 0, 0, 0);

    // 2) depthwise conv + SiLU
    conv_silu_kernel<<<4096, 256>>>(xzy, conv_wx, conv_wz, conv_wy, xc, cat, yc);

    // 3) x_dbl = xc @ x_proj_w^T   (4096x80, Kp=768)
    split_kernel<<<dim3(4096, 1), 256>>>(xc, 256, 0, 0, 1, 4096, 256, xcS, 0);
    split_kernel<<<dim3(80, 1), 256>>>(x_proj_w, 256, 0, 0, 1, 80, 256, wxpS, 1);
    gemm_mma<<<dim3(2, 32, 1), 256>>>(xcS, wxpS, xdbl, 4096, 80, 768,
        768, 768, 80, 0, nullptr, 0.f, 1.f, 0, 1, 0, 0, 0, 0, 0, 0);

    // 4) delta = softplus(dt @ dt_proj_w^T + 2*dt_proj_b)   (Kp=144)
    split_kernel<<<dim3(768, 1), 256>>>(xdbl, 80, 0, 0, 1, 4096, 48, dtS, 0);
    split_kernel<<<dim3(48, 1), 256>>>(dt_proj_w, 48, 0, 0, 1, 256, 48, wdtS, 1);
    gemm_mma<<<dim3(4, 32, 1), 256>>>(dtS, wdtS, delta, 4096, 256, 144,
        144, 144, 256, 0, dt_proj_b, 2.f, 1.f, 2, 1, 0, 0, 0, 0, 0, 0);

    // 5) selective scan -> cat cols [0,256)
    scan_kernel<<<64, 256>>>(delta, xc, xdbl, A_log, D_param, cat);

    // 6) qkv = yc @ qkv_w^T   (4096x768, Kp=768)
    split_kernel<<<dim3(4096, 1), 256>>>(yc, 256, 0, 0, 1, 4096, 256, ycS, 0);
    split_kernel<<<dim3(768, 1), 256>>>(qkv_w, 256, 0, 0, 1, 768, 256, wqkvS, 1);
    gemm_mma<<<dim3(12, 32, 1), 256>>>(ycS, wqkvS, qkv, 4096, 768, 768,
        768, 768, 768, 0, nullptr, 0.f, 1.f, 0, 1, 0, 0, 0, 0, 0, 0);

    // 7) fused flash attention -> o (4096x256)
    flash_kernel<<<dim3(8, 32), 256>>>(qkv, o);

    // 8) y_att = o @ attn_proj_w^T + b -> cat cols [512,768)
    split_kernel<<<dim3(4096, 1), 256>>>(o, 256, 0, 0, 1, 4096, 256, oS, 0);
    split_kernel<<<dim3(256, 1), 256>>>(attn_proj_w, 256, 0, 0, 1, 256, 256, watS, 1);
    gemm_mma<<<dim3(4, 32, 1), 256>>>(oS, watS, cat, 4096, 256, 768,
        768, 768, 768, 512, attn_proj_b, 1.f, 1.f, 1, 1, 0, 0, 0, 0, 0, 0);

    // 9) out = cat @ out_proj_w^T   (Kp=2304)
    split_kernel<<<dim3(12288, 1), 256>>>(cat, 768, 0, 0, 1, 4096, 768, catS, 0);
    split_kernel<<<dim3(2304, 1), 256>>>(out_proj_w, 768, 0, 0, 1, 768, 768, woutS, 1);
    gemm_mma<<<dim3(12, 32, 1), 256>>>(catS, woutS, out, 4096, 768, 2304,
        2304, 2304, 768, 0, nullptr, 0.f, 1.f, 0, 1, 0, 0, 0, 0, 0, 0);
}